// round 11
// baseline (speedup 1.0000x reference)
#include <cuda_runtime.h>
#include <cstdint>

#define B     64
#define F     3000
#define FSH   80
#define L     240000
#define EMPH  0.97f
#define NT    (B*F)
#define G     40          // frames emitted per group
#define NGRP  (F/G)       // 75 groups per batch -> 600 blocks, 4/SM resident
#define WARM  5           // warm-up frames: 0.97^(80*5) ~ 5e-6 state error
#define DEPTH 4           // cp.async ring depth
#define SLOT  128         // floats: 16 zero | 80 h | 16 an | 15 zero | 1 spare

// Scratch (static device arrays -- allocation-free per harness rules)
__device__ __align__(16) static float g_h [(size_t)NT*80];   // impulse responses
__device__ __align__(16) static float g_w [(size_t)NT*80];   // zero-state responses
__device__ __align__(16) static float g_an[(size_t)NT*16];   // an[j] = -a'[j+1], j=0..15

// ---- packed f32x2 helpers (FFMA2 is PTX-only on sm_103a) --------------------
__device__ __forceinline__ unsigned long long pk2(float x, float y) {
    unsigned long long r;
    asm("mov.b64 %0, {%1, %2};" : "=l"(r) : "f"(x), "f"(y));
    return r;
}
__device__ __forceinline__ void upk2(unsigned long long v, float& x, float& y) {
    asm("mov.b64 {%0, %1}, %2;" : "=f"(x), "=f"(y) : "l"(v));
}
__device__ __forceinline__ unsigned long long fma2(unsigned long long a,
                                                   unsigned long long b,
                                                   unsigned long long c) {
    unsigned long long d;
    asm("fma.rn.f32x2 %0, %1, %2, %3;" : "=l"(d) : "l"(a), "l"(b), "l"(c));
    return d;
}

// ---------------------------------------------------------------------------
// Kernel 1: NT threads, one per frame. The h-recursion and w-recursion share
// taps and structure, so both run as ONE packed f32x2 recursion:
//   x[m] = (delta[m], e[m]) + sum_j an[j] * x[m-j],  x = (h, w)
// -> 1280 FFMA2 per frame instead of 2560 FFMA. A warp owns 32 consecutive
// frames; e is staged coalesced into smem rows (stride 81, conflict-free),
// w overwrites e in place, h goes to a second row buffer; both copied out
// coalesced. 64-thread blocks keep static smem at 41.5 KB.
// ---------------------------------------------------------------------------
__global__ void __launch_bounds__(64) k_prep(const float* __restrict__ e,
                                             const float* __restrict__ lpc)
{
    __shared__ float bufA[2][32*81];   // e in, w out
    __shared__ float bufB[2][32*81];   // h out
    int t2 = blockIdx.x*64 + threadIdx.x;
    int wid  = threadIdx.x >> 5;
    int lane = threadIdx.x & 31;
    int wf0  = t2 - lane;              // warp's first frame
    float* rowA = bufA[wid] + lane*81;
    float* rowB = bufB[wid] + lane*81;
    float* bwA = bufA[wid];
    float* bwB = bufB[wid];

    float av[16];
    const float4* a4 = reinterpret_cast<const float4*>(lpc + (size_t)t2*16);
#pragma unroll
    for (int j = 0; j < 4; j++) {
        float4 t = a4[j];
        av[4*j+0]=t.x; av[4*j+1]=t.y; av[4*j+2]=t.z; av[4*j+3]=t.w;
    }

    // an[j] = -a'[j],  a'_j = a_j - EMPH*a_{j-1}  (a_0 = 1, a_16 = 0)
    float an[17];
    an[1] = EMPH - av[1];
#pragma unroll
    for (int j = 2; j <= 15; j++) an[j] = EMPH*av[j-1] - av[j];
    an[16] = EMPH*av[15];

    float4* anout = reinterpret_cast<float4*>(g_an + (size_t)t2*16);
#pragma unroll
    for (int j = 0; j < 16; j += 4)
        anout[j>>2] = make_float4(an[j+1], an[j+2], an[j+3], an[j+4]);

    // packed taps (an[j], an[j])
    unsigned long long anp[17];
#pragma unroll
    for (int j = 1; j <= 16; j++) anp[j] = pk2(an[j], an[j]);

    // stage e coalesced into bufA
    const float* eg = e + (size_t)wf0*80;
#pragma unroll 8
    for (int it = 0; it < 80; it++) {
        int i = it*32 + lane;
        bwA[i + i/80] = eg[i];                      // coalesced LDG.32
    }
    __syncwarp();

    // packed recursion: ring of 16 (h,w) pairs, static mod-16 indexing
    unsigned long long ring[16];
    {
        float h0, w0;
        ring[0] = pk2(1.f, rowA[0]);
        upk2(ring[0], h0, w0);
        rowB[0] = h0; rowA[0] = w0;
    }
#pragma unroll
    for (int m = 1; m < 16; m++) {
        unsigned long long part = pk2(0.f, rowA[m]);
#pragma unroll
        for (int j = 2; j <= m; j++) part = fma2(anp[j], ring[m-j], part);
        unsigned long long x = fma2(anp[1], ring[m-1], part);
        ring[m] = x;
        float hv, wv; upk2(x, hv, wv);
        rowB[m] = hv; rowA[m] = wv;
    }
#pragma unroll 1
    for (int base = 16; base < 80; base += 16) {    // base ≡ 0 (mod 16)
#pragma unroll
        for (int u = 0; u < 16; u++) {
            unsigned long long part = pk2(0.f, rowA[base + u]);
#pragma unroll
            for (int j = 2; j <= 16; j++)
                part = fma2(anp[j], ring[(u - j) & 15], part);
            unsigned long long x = fma2(anp[1], ring[(u - 1) & 15], part);
            ring[u & 15] = x;
            float hv, wv; upk2(x, hv, wv);
            rowB[base + u] = hv; rowA[base + u] = wv;
        }
    }
    __syncwarp();

    // coalesced copy-out of the warp's 2560-float spans
    float* dh = g_h + (size_t)wf0*80;
    float* dw = g_w + (size_t)wf0*80;
#pragma unroll 8
    for (int it = 0; it < 80; it++) {
        int i = it*32 + lane;
        dh[i] = bwB[i + i/80];                      // coalesced STG.32
        dw[i] = bwA[i + i/80];
    }
}

// ---------------------------------------------------------------------------
// cp.async prefetch of one frame's h (80f, 16B chunks into words 16..95) + an
// (16f, 16B chunks into words 96..111) into a ring slot.
// Words 0..15 and 112..126 are zero pads (written once at init).
// ---------------------------------------------------------------------------
__device__ __forceinline__ void fused_prefetch(uint32_t slot, size_t fg, int lane, bool valid)
{
    if (valid) {
        if (lane < 20)
            asm volatile("cp.async.ca.shared.global [%0], [%1], 16;"
                         :: "r"(slot + 64u + (uint32_t)lane*16u),
                            "l"(g_h + fg*80 + lane*4) : "memory");
        if (lane < 4)
            asm volatile("cp.async.ca.shared.global [%0], [%1], 16;"
                         :: "r"(slot + 384u + (uint32_t)lane*16u),
                            "l"(g_an + fg*16 + lane*4) : "memory");
    }
    asm volatile("cp.async.commit_group;" ::: "memory");
}

// ---------------------------------------------------------------------------
// Kernel 2: fused scan + output. One warp per (batch, group of G frames),
// WARM warm-up frames from zero state (group 0 exact). Lane l owns outputs
// m = 4l..4l+3 (lanes 0..19; lanes 20..31 shadow lane 19). Shuffle-free loop:
//   state s[t] = z_prev[79-t] lives in per-warp smem rb[31-t]
//   r[k] = sum_t an_s[k+t] * rb[31-t]   (broadcast LDS, zero-padded an)
//   z[m] = w[m] + sum_k r[k] h[m-k]     (5 overlapping float4 windows)
//   lanes 16..19 store z[64..79] back to rb for the next frame
// w via LDG.128 distance-2 register pipeline; h/an via cp.async ring.
// ---------------------------------------------------------------------------
__global__ void __launch_bounds__(256, 4) k_fused(float* __restrict__ out)
{
    __shared__ __align__(16) float ring[8][DEPTH][SLOT];
    __shared__ __align__(16) float rbuf[8][32];   // [0..15] r | [16..31] z-tail
    int w    = threadIdx.x >> 5;
    int lane = threadIdx.x & 31;
    size_t gg = (size_t)blockIdx.x*8 + w;
    int b = (int)(gg / NGRP), grp = (int)(gg - (size_t)b*NGRP);
    int f0 = grp * G;
    int fstart = (f0 >= WARM) ? f0 - WARM : 0;
    int warmcnt = f0 - fstart;
    int nfr = f0 + G - fstart;
    size_t fgbase = (size_t)b*F + fstart;
    uint32_t rbase = (uint32_t)__cvta_generic_to_shared(&ring[w][0][0]);
    float* rb = rbuf[w];

    // zero pads once: words 0..15 (left of h) and 112..126 (right of an)
    if (lane < 16) {
#pragma unroll
        for (int k = 0; k < DEPTH; k++) {
            ring[w][k][lane] = 0.f;
            if (lane < 15) ring[w][k][112 + lane] = 0.f;
        }
        rb[16 + lane] = 0.f;                 // initial state z_prev = 0
    }
    __syncwarp();

#pragma unroll
    for (int k = 0; k < DEPTH; k++)
        fused_prefetch(rbase + (uint32_t)k*SLOT*4u, fgbase + k, lane, k < nfr);

    int lane2 = (lane < 20) ? lane : 19;

    // w pipeline: float4 for frames j and j+1
    float4 wa, wb;
    {
        const float4* wp = reinterpret_cast<const float4*>(g_w + fgbase*80) + lane2;
        wa = wp[0];
        wb = (1 < nfr) ? wp[20] : make_float4(0.f,0.f,0.f,0.f);
    }

    float* outb = out + ((size_t)b*L + (size_t)fstart*FSH);
    int k16 = lane & 15;
    int tb  = (lane >> 4) << 3;          // 0 or 8

#pragma unroll 1
    for (int j = 0; j < nfr; j++) {
        asm volatile("cp.async.wait_group %0;" :: "n"(DEPTH-1) : "memory");
        __syncwarp();
        const float* slot = &ring[w][j & (DEPTH-1)][0];
        const float* an_s = slot + 96;     // an_s[i] = an[i+1]; [16..30] = 0

        // prefetch w for frame j+2
        float4 wc = make_float4(0.f,0.f,0.f,0.f);
        if (j + 2 < nfr)
            wc = reinterpret_cast<const float4*>(g_w + (fgbase + j + 2)*80)[lane2];

        // r[k]: halves t=0..7 / 8..15, combine via xor-16. s[t] read straight
        // from smem (2-way broadcast); zero-padded an kills range predicates.
        float part = 0.f;
#pragma unroll
        for (int t = 0; t < 8; t++) {
            int tt = tb + t;
            part = fmaf(an_s[k16 + tt], rb[31 - tt], part);
        }
        float r = part + __shfl_xor_sync(0xffffffffu, part, 16);
        if (lane < 16) rb[lane] = r;
        __syncwarp();

        // conv: z[4l+c] = w + sum_k r[k] h[4l+c-k].
        // word(h[x]) = x+16; windows p_i = slot4[lane2+4-i]; for k-quad kg:
        // fb = p_kg, fa = p_{kg+1}; term(c,j) = rq[j]*(c>=j ? fb[c-j] : fa[4+c-j])
        const float4* slot4 = reinterpret_cast<const float4*>(slot);
        float4 qf[5];
        qf[0] = slot4[lane2 + 4];
        qf[1] = slot4[lane2 + 3];
        qf[2] = slot4[lane2 + 2];
        qf[3] = slot4[lane2 + 1];
        qf[4] = slot4[lane2    ];

        float a0 = wa.x, a1 = wa.y, a2 = wa.z, a3 = wa.w;
#pragma unroll
        for (int kg = 0; kg < 4; kg++) {
            float4 fb = qf[kg];
            float4 fa = qf[kg + 1];
            float4 rq = reinterpret_cast<const float4*>(rb)[kg];  // broadcast
            a0 = fmaf(rq.x, fb.x, a0); a0 = fmaf(rq.y, fa.w, a0);
            a0 = fmaf(rq.z, fa.z, a0); a0 = fmaf(rq.w, fa.y, a0);
            a1 = fmaf(rq.x, fb.y, a1); a1 = fmaf(rq.y, fb.x, a1);
            a1 = fmaf(rq.z, fa.w, a1); a1 = fmaf(rq.w, fa.z, a1);
            a2 = fmaf(rq.x, fb.z, a2); a2 = fmaf(rq.y, fb.y, a2);
            a2 = fmaf(rq.z, fb.x, a2); a2 = fmaf(rq.w, fa.w, a2);
            a3 = fmaf(rq.x, fb.w, a3); a3 = fmaf(rq.y, fb.z, a3);
            a3 = fmaf(rq.z, fb.y, a3); a3 = fmaf(rq.w, fb.x, a3);
        }

        if (j >= warmcnt && lane < 20)     // emit only the group's own frames
            reinterpret_cast<float4*>(outb + (size_t)j*FSH)[lane] =
                make_float4(a0, a1, a2, a3);

        // next state: lanes 16..19 hold z[64..79]; store z[4l+c] at rb[4l+c-48]
        if (lane >= 16 && lane < 20)
            reinterpret_cast<float4*>(rb + 16)[lane - 16] =
                make_float4(a0, a1, a2, a3);

        wa = wb; wb = wc;

        __syncwarp();                      // slot consumed + state published
        fused_prefetch(rbase + (uint32_t)(j & (DEPTH-1))*SLOT*4u,
                       fgbase + j + DEPTH, lane, (j + DEPTH) < nfr);
    }
}

// ---------------------------------------------------------------------------
extern "C" void kernel_launch(void* const* d_in, const int* in_sizes, int n_in,
                              void* d_out, int out_size)
{
    (void)in_sizes; (void)n_in; (void)out_size;
    const float* e   = (const float*)d_in[0];   // excit (B, L, 1)
    const float* lpc = (const float*)d_in[1];   // lpc_coef (B, F, 16)
    float* out = (float*)d_out;                 // (B, L, 1)

    k_prep <<<NT/64, 64>>>(e, lpc);
    k_fused<<<(B*NGRP)/8, 256>>>(out);
}

// round 12
// speedup vs baseline: 1.0978x; 1.0978x over previous
#include <cuda_runtime.h>
#include <cstdint>

#define B     64
#define F     3000
#define FSH   80
#define L     240000
#define EMPH  0.97f
#define NT    (B*F)
#define G     30          // frames emitted per group
#define NGRP  (F/G)       // 100 groups per batch
#define WARM  4           // warm-up frames: 0.97^(80*4) ~ 6e-5 state error
#define DEPTH 4           // cp.async ring depth
#define SLOT  128         // floats: 16 zero | 80 h | 16 an | 15 zero | 1 spare

// Scratch (static device arrays -- allocation-free per harness rules)
__device__ __align__(16) static float g_h [(size_t)NT*80];   // impulse responses
__device__ __align__(16) static float g_w [(size_t)NT*80];   // zero-state responses
__device__ __align__(16) static float g_an[(size_t)NT*16];   // an[j] = -a'[j+1], j=0..15

// ---------------------------------------------------------------------------
// Kernel 1 (R10 proven version): 2*NT threads; first NT compute an + h,
// second NT compute w. A warp owns 32 CONSECUTIVE frames; its global I/O
// spans are contiguous. Rows staged in smem stride-81 (conflict-free);
// flat copies are coalesced scalar LDG/STG.
// ---------------------------------------------------------------------------
__global__ void __launch_bounds__(128) k_prep(const float* __restrict__ e,
                                              const float* __restrict__ lpc)
{
    __shared__ float buf[4][32*81];
    int tid = blockIdx.x*128 + threadIdx.x;
    bool do_w = (tid >= NT);                 // uniform per block (NT % 128 == 0)
    int t2 = do_w ? tid - NT : tid;
    int wid  = threadIdx.x >> 5;
    int lane = threadIdx.x & 31;
    int wf0  = t2 - lane;                    // warp's first frame
    float* bw = buf[wid];

    float av[16];
    const float4* a4 = reinterpret_cast<const float4*>(lpc + (size_t)t2*16);
#pragma unroll
    for (int j = 0; j < 4; j++) {
        float4 t = a4[j];
        av[4*j+0]=t.x; av[4*j+1]=t.y; av[4*j+2]=t.z; av[4*j+3]=t.w;
    }

    // an[j] = -a'[j],  a'_j = a_j - EMPH*a_{j-1}  (a_0 = 1, a_16 = 0)
    float an[17];
    an[1] = EMPH - av[1];
#pragma unroll
    for (int j = 2; j <= 15; j++) an[j] = EMPH*av[j-1] - av[j];
    an[16] = EMPH*av[15];

    if (!do_w) {
        // ---- h half: store an, compute h into smem row ----
        float4* anout = reinterpret_cast<float4*>(g_an + (size_t)t2*16);
#pragma unroll
        for (int j = 0; j < 16; j += 4)
            anout[j>>2] = make_float4(an[j+1], an[j+2], an[j+3], an[j+4]);

        float* row = bw + lane*81;
        float hr[32];

        hr[0] = 1.f;
        row[0] = 1.f;
#pragma unroll
        for (int m = 1; m < 16; m++) {
            float part = 0.f;
#pragma unroll
            for (int j = 2; j <= m; j++) part = fmaf(an[j], hr[m-j], part);
            hr[m] = fmaf(an[1], hr[m-1], part);
            row[m] = hr[m];
        }
#pragma unroll 1
        for (int base = 16; base < 80; base += 32) {   // base ≡ 16 (mod 32)
#pragma unroll
            for (int u = 0; u < 32; u++) {
                int mi = 16 + u;                       // static ring phase
                float part = 0.f;
#pragma unroll
                for (int j = 2; j <= 16; j++)
                    part = fmaf(an[j], hr[(mi - j) & 31], part);
                float acch = fmaf(an[1], hr[(mi - 1) & 31], part);
                hr[mi & 31] = acch;
                row[base + u] = acch;
            }
        }
    } else {
        // ---- w half: coalesced e -> smem, in-place recursion e -> w ----
        const float* eg = e + (size_t)wf0*80;
#pragma unroll 8
        for (int it = 0; it < 80; it++) {
            int i = it*32 + lane;
            bw[i + i/80] = eg[i];                      // coalesced LDG.32
        }
        __syncwarp();

        float* row = bw + lane*81;
        float wr[16];
#pragma unroll
        for (int m = 0; m < 16; m++) {
            float part = row[m];
#pragma unroll
            for (int j = 2; j <= m; j++) part = fmaf(an[j], wr[m-j], part);
            wr[m] = (m >= 1) ? fmaf(an[1], wr[m-1], part) : part;
            row[m] = wr[m];
        }
#pragma unroll 1
        for (int base = 16; base < 80; base += 16) {   // base ≡ 0 (mod 16)
#pragma unroll
            for (int u = 0; u < 16; u++) {
                int mi = u;                            // static ring phase
                float part = row[base + u];
#pragma unroll
                for (int j = 2; j <= 16; j++)
                    part = fmaf(an[j], wr[(mi - j) & 15], part);
                float accw = fmaf(an[1], wr[(mi - 1) & 15], part);
                wr[mi & 15] = accw;
                row[base + u] = accw;
            }
        }
    }
    __syncwarp();

    // coalesced copy-out of the warp's 2560-float span
    float* dst = (do_w ? g_w : g_h) + (size_t)wf0*80;
#pragma unroll 8
    for (int it = 0; it < 80; it++) {
        int i = it*32 + lane;
        dst[i] = bw[i + i/80];                         // coalesced STG.32
    }
}

// ---------------------------------------------------------------------------
// cp.async prefetch of one frame's h (80f, 16B chunks into words 16..95) + an
// (16f, 16B chunks into words 96..111) into a ring slot.
// Words 0..15 and 112..126 are zero pads (written once at init).
// ---------------------------------------------------------------------------
__device__ __forceinline__ void fused_prefetch(uint32_t slot, size_t fg, int lane, bool valid)
{
    if (valid) {
        if (lane < 20)
            asm volatile("cp.async.ca.shared.global [%0], [%1], 16;"
                         :: "r"(slot + 64u + (uint32_t)lane*16u),
                            "l"(g_h + fg*80 + lane*4) : "memory");
        if (lane < 4)
            asm volatile("cp.async.ca.shared.global [%0], [%1], 16;"
                         :: "r"(slot + 384u + (uint32_t)lane*16u),
                            "l"(g_an + fg*16 + lane*4) : "memory");
    }
    asm volatile("cp.async.commit_group;" ::: "memory");
}

// ---------------------------------------------------------------------------
// Kernel 2: fused scan + output. One warp per (batch, group of G frames),
// WARM warm-up frames from zero state (group 0 exact). Lane l owns outputs
// m = 4l..4l+3 (lanes 0..19; lanes 20..31 shadow lane 19). Shuffle-free loop:
//   state s[t] = z_prev[79-t] lives in per-warp smem rb[31-t]
//   r[k] = sum_t an_s[k+t] * rb[31-t]   (broadcast LDS, zero-padded an)
//   z[m] = w[m] + sum_k r[k] h[m-k]     (5 overlapping float4 windows)
//   lanes 16..19 store z[64..79] back to rb for the next frame
// 128-thread blocks (4 warps): reg cap gives 8 blocks/SM = 32 warps resident,
// and the 1600-block grid load-balances to ~ideal+2% per SM (vs +23% before).
// ---------------------------------------------------------------------------
__global__ void __launch_bounds__(128, 8) k_fused(float* __restrict__ out)
{
    __shared__ __align__(16) float ring[4][DEPTH][SLOT];
    __shared__ __align__(16) float rbuf[4][32];   // [0..15] r | [16..31] z-tail
    int w    = threadIdx.x >> 5;
    int lane = threadIdx.x & 31;
    size_t gg = (size_t)blockIdx.x*4 + w;
    int b = (int)(gg / NGRP), grp = (int)(gg - (size_t)b*NGRP);
    int f0 = grp * G;
    int fstart = (f0 >= WARM) ? f0 - WARM : 0;
    int warmcnt = f0 - fstart;
    int nfr = f0 + G - fstart;
    size_t fgbase = (size_t)b*F + fstart;
    uint32_t rbase = (uint32_t)__cvta_generic_to_shared(&ring[w][0][0]);
    float* rb = rbuf[w];

    // zero pads once: words 0..15 (left of h) and 112..126 (right of an)
    if (lane < 16) {
#pragma unroll
        for (int k = 0; k < DEPTH; k++) {
            ring[w][k][lane] = 0.f;
            if (lane < 15) ring[w][k][112 + lane] = 0.f;
        }
        rb[16 + lane] = 0.f;                 // initial state z_prev = 0
    }
    __syncwarp();

#pragma unroll
    for (int k = 0; k < DEPTH; k++)
        fused_prefetch(rbase + (uint32_t)k*SLOT*4u, fgbase + k, lane, k < nfr);

    int lane2 = (lane < 20) ? lane : 19;

    // w pipeline: float4 for frames j and j+1
    float4 wa, wb;
    {
        const float4* wp = reinterpret_cast<const float4*>(g_w + fgbase*80) + lane2;
        wa = wp[0];
        wb = (1 < nfr) ? wp[20] : make_float4(0.f,0.f,0.f,0.f);
    }

    float* outb = out + ((size_t)b*L + (size_t)fstart*FSH);
    int k16 = lane & 15;
    int tb  = (lane >> 4) << 3;          // 0 or 8

#pragma unroll 1
    for (int j = 0; j < nfr; j++) {
        asm volatile("cp.async.wait_group %0;" :: "n"(DEPTH-1) : "memory");
        __syncwarp();
        const float* slot = &ring[w][j & (DEPTH-1)][0];
        const float* an_s = slot + 96;     // an_s[i] = an[i+1]; [16..30] = 0

        // prefetch w for frame j+2
        float4 wc = make_float4(0.f,0.f,0.f,0.f);
        if (j + 2 < nfr)
            wc = reinterpret_cast<const float4*>(g_w + (fgbase + j + 2)*80)[lane2];

        // r[k]: halves t=0..7 / 8..15, combine via xor-16. s[t] read straight
        // from smem (2-way broadcast); zero-padded an kills range predicates.
        float part = 0.f;
#pragma unroll
        for (int t = 0; t < 8; t++) {
            int tt = tb + t;
            part = fmaf(an_s[k16 + tt], rb[31 - tt], part);
        }
        float r = part + __shfl_xor_sync(0xffffffffu, part, 16);
        if (lane < 16) rb[lane] = r;
        __syncwarp();

        // conv: z[4l+c] = w + sum_k r[k] h[4l+c-k].
        // word(h[x]) = x+16; windows p_i = slot4[lane2+4-i]; for k-quad kg:
        // fb = p_kg, fa = p_{kg+1}; term(c,j) = rq[j]*(c>=j ? fb[c-j] : fa[4+c-j])
        const float4* slot4 = reinterpret_cast<const float4*>(slot);
        float4 qf[5];
        qf[0] = slot4[lane2 + 4];
        qf[1] = slot4[lane2 + 3];
        qf[2] = slot4[lane2 + 2];
        qf[3] = slot4[lane2 + 1];
        qf[4] = slot4[lane2    ];

        float a0 = wa.x, a1 = wa.y, a2 = wa.z, a3 = wa.w;
#pragma unroll
        for (int kg = 0; kg < 4; kg++) {
            float4 fb = qf[kg];
            float4 fa = qf[kg + 1];
            float4 rq = reinterpret_cast<const float4*>(rb)[kg];  // broadcast
            a0 = fmaf(rq.x, fb.x, a0); a0 = fmaf(rq.y, fa.w, a0);
            a0 = fmaf(rq.z, fa.z, a0); a0 = fmaf(rq.w, fa.y, a0);
            a1 = fmaf(rq.x, fb.y, a1); a1 = fmaf(rq.y, fb.x, a1);
            a1 = fmaf(rq.z, fa.w, a1); a1 = fmaf(rq.w, fa.z, a1);
            a2 = fmaf(rq.x, fb.z, a2); a2 = fmaf(rq.y, fb.y, a2);
            a2 = fmaf(rq.z, fb.x, a2); a2 = fmaf(rq.w, fa.w, a2);
            a3 = fmaf(rq.x, fb.w, a3); a3 = fmaf(rq.y, fb.z, a3);
            a3 = fmaf(rq.z, fb.y, a3); a3 = fmaf(rq.w, fb.x, a3);
        }

        if (j >= warmcnt && lane < 20)     // emit only the group's own frames
            reinterpret_cast<float4*>(outb + (size_t)j*FSH)[lane] =
                make_float4(a0, a1, a2, a3);

        // next state: lanes 16..19 hold z[64..79]; store z[4l+c] at rb[4l+c-48]
        if (lane >= 16 && lane < 20)
            reinterpret_cast<float4*>(rb + 16)[lane - 16] =
                make_float4(a0, a1, a2, a3);

        wa = wb; wb = wc;

        __syncwarp();                      // slot consumed + state published
        fused_prefetch(rbase + (uint32_t)(j & (DEPTH-1))*SLOT*4u,
                       fgbase + j + DEPTH, lane, (j + DEPTH) < nfr);
    }
}

// ---------------------------------------------------------------------------
extern "C" void kernel_launch(void* const* d_in, const int* in_sizes, int n_in,
                              void* d_out, int out_size)
{
    (void)in_sizes; (void)n_in; (void)out_size;
    const float* e   = (const float*)d_in[0];   // excit (B, L, 1)
    const float* lpc = (const float*)d_in[1];   // lpc_coef (B, F, 16)
    float* out = (float*)d_out;                 // (B, L, 1)

    k_prep <<<(2*NT)/128, 128>>>(e, lpc);
    k_fused<<<(B*NGRP)/4, 128>>>(out);
}